// round 2
// baseline (speedup 1.0000x reference)
#include <cuda_runtime.h>
#include <cstdint>

// Problem constants
#define N_TOK   131072          // 32*4096 tokens
#define DIM     64
#define NE      512
#define ROWF    80              // padded floats per smem code row (320B: 2-way fill conflicts, 16B aligned)
#define SMEM_E_BYTES (NE * ROWF * 4)          // 163840
#define SMEM_TOTAL   (SMEM_E_BYTES + NE * 4)  // + sq_e[512] = 165888 B

// Output layout (all fp32, concatenated in reference return order)
#define OUT_Q     0ull          // quantize_st: 8388608
#define OUT_DIFF  8388608ull    // diff: 1
#define OUT_IND   8388609ull    // embed_ind: 131072
#define OUT_EMB   8519681ull    // new_embed: 32768
#define OUT_CS    8552449ull    // new_cluster_size: 512
#define OUT_AVG   8552961ull    // new_embed_avg: 32768

// Scratch (device globals — no allocation allowed)
__device__ float        g_embed_sum[DIM * NE];
__device__ unsigned int g_hist[NE];
__device__ double       g_diff;

static __device__ __forceinline__ unsigned long long fma2(unsigned long long a,
                                                          unsigned long long b,
                                                          unsigned long long c) {
    unsigned long long d;
    asm("fma.rn.f32x2 %0, %1, %2, %3;" : "=l"(d) : "l"(a), "l"(b), "l"(c));
    return d;
}
static __device__ __forceinline__ unsigned long long add2(unsigned long long a,
                                                          unsigned long long b) {
    unsigned long long d;
    asm("add.rn.f32x2 %0, %1, %2;" : "=l"(d) : "l"(a), "l"(b));
    return d;
}
static __device__ __forceinline__ float lo32(unsigned long long v) {
    return __uint_as_float((unsigned)v);
}
static __device__ __forceinline__ float hi32(unsigned long long v) {
    return __uint_as_float((unsigned)(v >> 32));
}

__global__ void vq_init() {
    int i = blockIdx.x * blockDim.x + threadIdx.x;
    if (i < DIM * NE) g_embed_sum[i] = 0.0f;
    if (i < NE)       g_hist[i] = 0u;
    if (i == 0)       g_diff = 0.0;
}

__global__ __launch_bounds__(512, 1)
void vq_main(const float* __restrict__ x, const float* __restrict__ embed,
             float* __restrict__ out) {
    extern __shared__ float sm[];
    float* sE = sm;               // [NE][ROWF] code rows, dim-contiguous
    float* sq = sm + NE * ROWF;   // [NE] ||E_e||^2
    const int tid = threadIdx.x;

    // Fill SMEM codebook transposed: embed is [d][e] (e fastest) -> sE[e][d].
    // Global reads fully coalesced; stores stride 320B -> 2-way conflicts (one-time).
    for (int idx = tid; idx < DIM * NE; idx += 512) {
        int d = idx >> 9;
        int e = idx & (NE - 1);
        sE[e * ROWF + d] = embed[idx];
    }
    __syncthreads();

    // ||E_e||^2 per code (fp32, tiny magnitude — ordering irrelevant to argmin grid)
    {
        const float* r = sE + tid * ROWF;
        float s = 0.0f;
#pragma unroll
        for (int d = 0; d < DIM; d++) s = __fmaf_rn(r[d], r[d], s);
        sq[tid] = s;
    }
    __syncthreads();

    // One token per thread; grid-stride over tokens.
    for (int tok = blockIdx.x * 512 + tid; tok < N_TOK; tok += gridDim.x * 512) {
        // Load f as 32 packed f32x2 pairs (f[2i], f[2i+1])
        unsigned long long fq[32];
        const ulonglong2* xr = (const ulonglong2*)(x + (size_t)tok * DIM);
#pragma unroll
        for (int i = 0; i < 16; i++) {
            ulonglong2 v = xr[i];
            fq[2 * i]     = v.x;
            fq[2 * i + 1] = v.y;
        }

        // ||f||^2 (constant per token — shared across all codes, cannot flip argmin)
        unsigned long long s2a = 0ull, s2b = 0ull;
#pragma unroll
        for (int i = 0; i < 32; i += 2) {
            s2a = fma2(fq[i],     fq[i],     s2a);
            s2b = fma2(fq[i + 1], fq[i + 1], s2b);
        }
        unsigned long long s2 = add2(s2a, s2b);
        float sumf = lo32(s2) + hi32(s2);

        float best = 3.4028235e38f;
        int   bi   = 0;

        // 512 codes: per code 16x LDS.128 (broadcast) + 32x FFMA2 -> fp32-pipe bound
        for (int e = 0; e < NE; e++) {
            const char* rb = (const char*)sE + e * (ROWF * 4);
            unsigned long long a0 = 0ull, a1 = 0ull, a2 = 0ull, a3 = 0ull;
#pragma unroll
            for (int c = 0; c < 16; c += 2) {
                ulonglong2 v0 = *(const ulonglong2*)(rb + c * 16);
                ulonglong2 v1 = *(const ulonglong2*)(rb + c * 16 + 16);
                a0 = fma2(fq[2 * c],     v0.x, a0);
                a1 = fma2(fq[2 * c + 1], v0.y, a1);
                a2 = fma2(fq[2 * c + 2], v1.x, a2);
                a3 = fma2(fq[2 * c + 3], v1.y, a3);
            }
            unsigned long long s = add2(add2(a0, a2), add2(a1, a3));
            float dot  = lo32(s) + hi32(s);
            // Match reference rounding: (sumf - 2*dot) then + ||E||^2
            float t    = __fmaf_rn(-2.0f, dot, sumf);
            float dist = t + sq[e];
            if (dist < best) { best = dist; bi = e; }  // strict < keeps first index (argmin tie rule)
        }

        const int ind = bi;
        out[OUT_IND + tok] = (float)ind;
        atomicAdd(&g_hist[ind], 1u);

        // Gather code row, write quantize_st, accumulate diff + segment sum
        const float* qr = sE + ind * ROWF;
        float4* oq = (float4*)(out + OUT_Q + (size_t)tok * DIM);
        float dsum = 0.0f;
#pragma unroll
        for (int i = 0; i < 16; i++) {
            float fx0 = lo32(fq[2 * i]),     fx1 = hi32(fq[2 * i]);
            float fx2 = lo32(fq[2 * i + 1]), fx3 = hi32(fq[2 * i + 1]);
            float q0 = qr[4 * i + 0], q1 = qr[4 * i + 1];
            float q2 = qr[4 * i + 2], q3 = qr[4 * i + 3];
            float d0 = q0 - fx0, d1 = q1 - fx1, d2 = q2 - fx2, d3 = q3 - fx3;
            dsum += d0 * d0 + d1 * d1 + d2 * d2 + d3 * d3;
            float4 st;                       // quantize_st = x + (q - x), reference rounding
            st.x = fx0 + d0; st.y = fx1 + d1; st.z = fx2 + d2; st.w = fx3 + d3;
            oq[i] = st;
            atomicAdd(&g_embed_sum[(4 * i + 0) * NE + ind], fx0);
            atomicAdd(&g_embed_sum[(4 * i + 1) * NE + ind], fx1);
            atomicAdd(&g_embed_sum[(4 * i + 2) * NE + ind], fx2);
            atomicAdd(&g_embed_sum[(4 * i + 3) * NE + ind], fx3);
        }
        // diff partial: warp-reduce then one double atomic per warp
#pragma unroll
        for (int o = 16; o; o >>= 1) dsum += __shfl_xor_sync(0xffffffffu, dsum, o);
        if ((tid & 31) == 0) atomicAdd(&g_diff, (double)dsum);
    }
}

__global__ void vq_fin(const float* __restrict__ cs_in, const float* __restrict__ ea_in,
                       float* __restrict__ out) {
    __shared__ float sn[512];
    const int e = threadIdx.x;

    float h   = (float)g_hist[e];
    float ncs = cs_in[e] * 0.99f + 0.01f * h;   // new_cluster_size
    out[OUT_CS + e] = ncs;

    sn[e] = ncs;
    __syncthreads();
    for (int o = 256; o; o >>= 1) {
        if (e < o) sn[e] += sn[e + o];
        __syncthreads();
    }
    const float n   = sn[0];
    const float csn = (ncs + 1e-5f) / (n + 0.00512f) * n;  // Laplace-smoothed cluster size

#pragma unroll 4
    for (int d = 0; d < DIM; d++) {
        int idx = d * NE + e;
        float avg = ea_in[idx] * 0.99f + 0.01f * g_embed_sum[idx];
        out[OUT_AVG + idx] = avg;              // new_embed_avg
        out[OUT_EMB + idx] = avg / csn;        // new_embed
    }

    if (e == 0) out[OUT_DIFF] = (float)(g_diff * (1.0 / 8388608.0));
}

extern "C" void kernel_launch(void* const* d_in, const int* in_sizes, int n_in,
                              void* d_out, int out_size) {
    const float* x     = (const float*)d_in[0];
    const float* embed = (const float*)d_in[1];
    const float* cs    = (const float*)d_in[2];
    const float* ea    = (const float*)d_in[3];
    float* out = (float*)d_out;

    cudaFuncSetAttribute(vq_main, cudaFuncAttributeMaxDynamicSharedMemorySize, SMEM_TOTAL);

    vq_init<<<64, 512>>>();
    vq_main<<<148, 512, SMEM_TOTAL>>>(x, embed, out);
    vq_fin<<<1, 512>>>(cs, ea, out);
}

// round 6
// speedup vs baseline: 1.4266x; 1.4266x over previous
#include <cuda_runtime.h>
#include <cuda_bf16.h>
#include <cstdint>

#define N_TOK   131072
#define DIM     64
#define NE      512
#define TILE_M  256
#define N_TILES 512
#define NTHR    256
#define TAU     1e-4f

#define OUT_Q     0ull
#define OUT_DIFF  8388608ull
#define OUT_IND   8388609ull
#define OUT_EMB   8519681ull
#define OUT_CS    8552449ull
#define OUT_AVG   8552961ull

#define SB_HI   0
#define SB_LO   65536
#define SA_HI   131072
#define SA_LO   163840
#define SSQ     196608
#define SSQO    198656          // ||E||^2 + 0.5
#define SSF     200704
#define SIND    201728
#define SHIST   202752
#define SLIST   204800
#define SCNT    205824
#define SMEM_TOTAL 205840

#define SWZ(o) ((o) ^ (((o) >> 3) & 0x70))

__device__ float        g_embed_sum[NE * DIM];
__device__ unsigned int g_hist[NE];
__device__ double       g_diff;

static __device__ __forceinline__ uint32_t smem_u32(const void* p) {
    uint32_t a;
    asm("{ .reg .u64 t; cvta.to.shared.u64 t, %1; cvt.u32.u64 %0, t; }" : "=r"(a) : "l"(p));
    return a;
}
static __device__ __forceinline__ float bff(uint32_t u) {
    return __bfloat162float(__ushort_as_bfloat16((unsigned short)(u & 0xFFFFu)));
}
static __device__ __forceinline__ uint32_t b2u(__nv_bfloat162 v) {
    uint32_t u; memcpy(&u, &v, 4); return u;
}
static __device__ __forceinline__ void mma16816(float* c, const uint32_t* a,
                                                const uint32_t* b) {
    asm volatile(
        "mma.sync.aligned.m16n8k16.row.col.f32.bf16.bf16.f32 "
        "{%0,%1,%2,%3}, {%4,%5,%6,%7}, {%8,%9}, {%0,%1,%2,%3};"
        : "+f"(c[0]), "+f"(c[1]), "+f"(c[2]), "+f"(c[3])
        : "r"(a[0]), "r"(a[1]), "r"(a[2]), "r"(a[3]), "r"(b[0]), "r"(b[1]));
}
static __device__ __forceinline__ void ldsm4(uint32_t* r, uint32_t addr) {
    asm volatile("ldmatrix.sync.aligned.m8n8.x4.shared.b16 {%0,%1,%2,%3}, [%4];"
                 : "=r"(r[0]), "=r"(r[1]), "=r"(r[2]), "=r"(r[3]) : "r"(addr));
}
static __device__ __forceinline__ void top2(uint32_t& k1, uint32_t& k2, uint32_t k) {
    uint32_t mx = k > k1 ? k : k1;       // loser of (k, k1)
    k1 = k < k1 ? k : k1;
    k2 = mx < k2 ? mx : k2;
}

__global__ void vq_init() {
    int i = blockIdx.x * blockDim.x + threadIdx.x;
    if (i < NE * DIM) g_embed_sum[i] = 0.0f;
    if (i < NE)       g_hist[i] = 0u;
    if (i == 0)       g_diff = 0.0;
}

__global__ __launch_bounds__(NTHR, 1)
void vq_main(const float* __restrict__ x, const float* __restrict__ embed,
             float* __restrict__ out) {
    extern __shared__ char smc[];
    float*        ssq   = (float*)(smc + SSQ);
    float*        ssqo  = (float*)(smc + SSQO);
    float*        ssf   = (float*)(smc + SSF);
    int*          sind  = (int*)(smc + SIND);
    unsigned int* shist = (unsigned int*)(smc + SHIST);
    int*          slist = (int*)(smc + SLIST);
    int*          scnt  = (int*)(smc + SCNT);

    const int tid  = threadIdx.x;
    const int lane = tid & 31;
    const int w    = tid >> 5;
    const uint32_t sbase = smem_u32(smc);

    for (int e = tid; e < NE; e += NTHR) shist[e] = 0u;
    for (int idx = tid; idx < DIM * NE; idx += NTHR) {
        int d = idx >> 9;
        int e = idx & (NE - 1);
        float v = embed[idx];
        __nv_bfloat16 h = __float2bfloat16(v);
        __nv_bfloat16 l = __float2bfloat16(v - __bfloat162float(h));
        uint32_t so = SWZ((uint32_t)(e * 128 + d * 2));
        *(__nv_bfloat16*)(smc + SB_HI + so) = h;
        *(__nv_bfloat16*)(smc + SB_LO + so) = l;
    }
    for (int e = tid; e < NE; e += NTHR) {
        float s = 0.0f;
#pragma unroll
        for (int d = 0; d < DIM; d++) {
            float v = embed[d * NE + e];
            s = __fmaf_rn(v, v, s);
        }
        ssq[e]  = s;
        ssqo[e] = s + 0.5f;
    }
    __syncthreads();

    const int mat  = lane >> 3;
    const int mrow = lane & 7;
    const int q    = lane >> 2;
    const int cq   = lane & 3;

    for (int tile = blockIdx.x; tile < N_TILES; tile += gridDim.x) {
        // ---- phase 1: bf16 split + ||f||^2 ----
        if (tid == 0) *scnt = 0;
        const float4* xr = (const float4*)x + ((size_t)tile * TILE_M + tid) * 16;
        float s0 = 0.f, s1 = 0.f, s2 = 0.f, s3 = 0.f;
#pragma unroll
        for (int i = 0; i < 16; i++) {
            float4 v = xr[i];
            s0 = __fmaf_rn(v.x, v.x, s0);
            s1 = __fmaf_rn(v.y, v.y, s1);
            s2 = __fmaf_rn(v.z, v.z, s2);
            s3 = __fmaf_rn(v.w, v.w, s3);
            __nv_bfloat162 hA = __float22bfloat162_rn(make_float2(v.x, v.y));
            __nv_bfloat162 hB = __float22bfloat162_rn(make_float2(v.z, v.w));
            float2 hAf = __bfloat1622float2(hA);
            float2 hBf = __bfloat1622float2(hB);
            __nv_bfloat162 lA = __float22bfloat162_rn(make_float2(v.x - hAf.x, v.y - hAf.y));
            __nv_bfloat162 lB = __float22bfloat162_rn(make_float2(v.z - hBf.x, v.w - hBf.y));
            uint32_t so = SWZ((uint32_t)(tid * 128 + i * 8));
            *(uint2*)(smc + SA_HI + so) = make_uint2(b2u(hA), b2u(hB));
            *(uint2*)(smc + SA_LO + so) = make_uint2(b2u(lA), b2u(lB));
        }
        ssf[tid] = (s0 + s1) + (s2 + s3);
        __syncthreads();

        // ---- phase 2: MMA scan, warp owns 32 tokens; top-2 keys per row ----
        uint32_t AH[2][4][4], AL[2][4][4];
#pragma unroll
        for (int mt = 0; mt < 2; mt++)
#pragma unroll
            for (int ks = 0; ks < 4; ks++) {
                int trow = w * 32 + mt * 16 + (mat & 1) * 8 + mrow;
                uint32_t off = SWZ((uint32_t)(trow * 128 + ks * 32 + (mat >> 1) * 16));
                ldsm4(AH[mt][ks], sbase + SA_HI + off);
                ldsm4(AL[mt][ks], sbase + SA_LO + off);
            }
        uint32_t k1[4] = {~0u, ~0u, ~0u, ~0u};
        uint32_t k2[4] = {~0u, ~0u, ~0u, ~0u};

#pragma unroll 1
        for (int nb = 0; nb < NE; nb += 16) {
            uint32_t BH[4][4], BL[4][4];
#pragma unroll
            for (int ks = 0; ks < 4; ks++) {
                int code = nb + (mat >> 1) * 8 + mrow;
                uint32_t off = SWZ((uint32_t)(code * 128 + ks * 32 + (mat & 1) * 16));
                ldsm4(BH[ks], sbase + SB_HI + off);
                ldsm4(BL[ks], sbase + SB_LO + off);
            }
            float acc[2][2][4];
#pragma unroll
            for (int mt = 0; mt < 2; mt++)
#pragma unroll
                for (int nt = 0; nt < 2; nt++)
#pragma unroll
                    for (int r = 0; r < 4; r++) acc[mt][nt][r] = 0.0f;
#pragma unroll
            for (int ks = 0; ks < 4; ks++)
#pragma unroll
                for (int mt = 0; mt < 2; mt++) {
                    mma16816(acc[mt][0], AH[mt][ks], &BH[ks][0]);
                    mma16816(acc[mt][1], AH[mt][ks], &BH[ks][2]);
                    mma16816(acc[mt][0], AH[mt][ks], &BL[ks][0]);
                    mma16816(acc[mt][1], AH[mt][ks], &BL[ks][2]);
                    mma16816(acc[mt][0], AL[mt][ks], &BH[ks][0]);
                    mma16816(acc[mt][1], AL[mt][ks], &BH[ks][2]);
                }
            float2 sqa = *(const float2*)(ssqo + nb + 2 * cq);
            float2 sqb = *(const float2*)(ssqo + nb + 8 + 2 * cq);
            const uint32_t c0 = (uint32_t)(nb + 2 * cq);
#pragma unroll
            for (int mt = 0; mt < 2; mt++)
#pragma unroll
                for (int hr = 0; hr < 2; hr++) {
                    int row = mt * 2 + hr;
                    float m0 = __fmaf_rn(-2.f, acc[mt][0][hr * 2 + 0], sqa.x);
                    float m1 = __fmaf_rn(-2.f, acc[mt][0][hr * 2 + 1], sqa.y);
                    float m2 = __fmaf_rn(-2.f, acc[mt][1][hr * 2 + 0], sqb.x);
                    float m3 = __fmaf_rn(-2.f, acc[mt][1][hr * 2 + 1], sqb.y);
                    top2(k1[row], k2[row], (__float_as_uint(m0) & 0xFFFFFE00u) | c0);
                    top2(k1[row], k2[row], (__float_as_uint(m1) & 0xFFFFFE00u) | (c0 + 1));
                    top2(k1[row], k2[row], (__float_as_uint(m2) & 0xFFFFFE00u) | (c0 + 8));
                    top2(k1[row], k2[row], (__float_as_uint(m3) & 0xFFFFFE00u) | (c0 + 9));
                }
        }
#pragma unroll
        for (int r = 0; r < 4; r++) {
            uint32_t b1 = k1[r], b2 = k2[r];
#pragma unroll
            for (int off = 1; off < 4; off <<= 1) {
                uint32_t o1 = __shfl_xor_sync(0xffffffffu, b1, off);
                uint32_t o2 = __shfl_xor_sync(0xffffffffu, b2, off);
                uint32_t mx = b1 > o1 ? b1 : o1;
                b1 = b1 < o1 ? b1 : o1;
                b2 = b2 < o2 ? b2 : o2;
                b2 = mx < b2 ? mx : b2;
            }
            if (cq == 0) {
                int token = w * 32 + q + r * 8;
                sind[token] = (int)(b1 & 0x1FFu);
                float f1 = __uint_as_float(b1 & 0xFFFFFE00u);
                float f2 = __uint_as_float(b2 & 0xFFFFFE00u);
                if (f2 - f1 < TAU) {
                    int idx = atomicAdd(scnt, 1);
                    slist[idx] = token;
                }
            }
        }
        __syncthreads();

        // ---- phase 2b: exact fp32 rescore of flagged tokens (warp-cooperative) ----
        const int cnt = *scnt;
        for (int i = w; i < cnt; i += 8) {
            const int t = slist[i];
            float xv[DIM];
            const float4* xrr = (const float4*)(x + ((size_t)tile * TILE_M + t) * DIM);
#pragma unroll
            for (int j = 0; j < 16; j++) {
                float4 v = xrr[j];
                xv[4 * j] = v.x; xv[4 * j + 1] = v.y;
                xv[4 * j + 2] = v.z; xv[4 * j + 3] = v.w;
            }
            const float sumf = ssf[t];
            float bb = 3.4028235e38f;
            int   be = 0;
#pragma unroll 1
            for (int g = 0; g < 16; g++) {
                int e = g * 32 + lane;
                float dot = 0.0f;
#pragma unroll
                for (int d = 0; d < DIM; d++)
                    dot = __fmaf_rn(xv[d], embed[d * NE + e], dot);
                float dist = __fmaf_rn(-2.0f, dot, sumf) + ssq[e];
                if (dist < bb) { bb = dist; be = e; }
            }
#pragma unroll
            for (int off = 16; off; off >>= 1) {
                float ob = __shfl_xor_sync(0xffffffffu, bb, off);
                int   oe = __shfl_xor_sync(0xffffffffu, be, off);
                if (ob < bb || (ob == bb && oe < be)) { bb = ob; be = oe; }
            }
            if (lane == 0) sind[t] = be;
        }
        __syncthreads();

        // ---- phase 3: epilogue ----
        const int gt  = tile * TILE_M + tid;
        const int ind = sind[tid];
        out[OUT_IND + gt] = (float)ind;
        atomicAdd(&shist[ind], 1u);

        const float4* xr2 = (const float4*)x + (size_t)gt * 16;
        float4* oq = (float4*)(out + OUT_Q + (size_t)gt * DIM);
        float*  es = g_embed_sum + ind * DIM;
        float dsum = 0.0f;
#pragma unroll
        for (int j = 0; j < 8; j++) {
            uint32_t qoff = SWZ((uint32_t)(ind * 128 + j * 16));
            uint4 hq = *(const uint4*)(smc + SB_HI + qoff);
            uint4 lq = *(const uint4*)(smc + SB_LO + qoff);
            float q0 = bff(hq.x) + bff(lq.x), q1 = bff(hq.x >> 16) + bff(lq.x >> 16);
            float q2 = bff(hq.y) + bff(lq.y), q3 = bff(hq.y >> 16) + bff(lq.y >> 16);
            float q4 = bff(hq.z) + bff(lq.z), q5 = bff(hq.z >> 16) + bff(lq.z >> 16);
            float q6 = bff(hq.w) + bff(lq.w), q7 = bff(hq.w >> 16) + bff(lq.w >> 16);
            float4 xa = xr2[2 * j];
            float4 xb = xr2[2 * j + 1];
            float e0 = q0 - xa.x, e1 = q1 - xa.y, e2 = q2 - xa.z, e3 = q3 - xa.w;
            float e4 = q4 - xb.x, e5 = q5 - xb.y, e6 = q6 - xb.z, e7 = q7 - xb.w;
            dsum += e0 * e0 + e1 * e1 + e2 * e2 + e3 * e3
                  + e4 * e4 + e5 * e5 + e6 * e6 + e7 * e7;
            oq[2 * j]     = make_float4(xa.x + e0, xa.y + e1, xa.z + e2, xa.w + e3);
            oq[2 * j + 1] = make_float4(xb.x + e4, xb.y + e5, xb.z + e6, xb.w + e7);
            atomicAdd(&es[8 * j + 0], xa.x);
            atomicAdd(&es[8 * j + 1], xa.y);
            atomicAdd(&es[8 * j + 2], xa.z);
            atomicAdd(&es[8 * j + 3], xa.w);
            atomicAdd(&es[8 * j + 4], xb.x);
            atomicAdd(&es[8 * j + 5], xb.y);
            atomicAdd(&es[8 * j + 6], xb.z);
            atomicAdd(&es[8 * j + 7], xb.w);
        }
#pragma unroll
        for (int o = 16; o; o >>= 1) dsum += __shfl_xor_sync(0xffffffffu, dsum, o);
        if (lane == 0) atomicAdd(&g_diff, (double)dsum);

        __syncthreads();
    }

    for (int e = tid; e < NE; e += NTHR)
        if (shist[e]) atomicAdd(&g_hist[e], shist[e]);
}

__global__ void vq_fin(const float* __restrict__ cs_in, const float* __restrict__ ea_in,
                       float* __restrict__ out) {
    __shared__ float sn[512];
    const int e = threadIdx.x;

    float h   = (float)g_hist[e];
    float ncs = cs_in[e] * 0.99f + 0.01f * h;
    out[OUT_CS + e] = ncs;

    sn[e] = ncs;
    __syncthreads();
    for (int o = 256; o; o >>= 1) {
        if (e < o) sn[e] += sn[e + o];
        __syncthreads();
    }
    const float n   = sn[0];
    const float csn = (ncs + 1e-5f) / (n + 0.00512f) * n;

#pragma unroll 4
    for (int d = 0; d < DIM; d++) {
        int idx = d * NE + e;
        float avg = ea_in[idx] * 0.99f + 0.01f * g_embed_sum[e * DIM + d];
        out[OUT_AVG + idx] = avg;
        out[OUT_EMB + idx] = avg / csn;
    }
    if (e == 0) out[OUT_DIFF] = (float)(g_diff * (1.0 / 8388608.0));
}

extern "C" void kernel_launch(void* const* d_in, const int* in_sizes, int n_in,
                              void* d_out, int out_size) {
    const float* x     = (const float*)d_in[0];
    const float* embed = (const float*)d_in[1];
    const float* cs    = (const float*)d_in[2];
    const float* ea    = (const float*)d_in[3];
    float* out = (float*)d_out;

    cudaFuncSetAttribute(vq_main, cudaFuncAttributeMaxDynamicSharedMemorySize, SMEM_TOTAL);

    vq_init<<<64, 512>>>();
    vq_main<<<148, NTHR, SMEM_TOTAL>>>(x, embed, out);
    vq_fin<<<1, 512>>>(cs, ea, out);
}